// round 9
// baseline (speedup 1.0000x reference)
#include <cuda_runtime.h>
#include <cuda_fp16.h>
#include <stdint.h>

// ---------------- problem constants ----------------
#define N_USERS  50000
#define N_ITEMS  100000
#define N_NODES  (N_USERS + N_ITEMS)     // 150000
#define N_EDGES  2400000
#define DIM      64
#define BATCH    4096

#define TOTAL    (N_NODES * DIM)         // 9,600,000 floats
#define TOT8     (TOTAL / 8)             // uint4-of-half count per buffer

#define SCAN_B   1024
#define NBLK     ((N_NODES + SCAN_B - 1) / SCAN_B)   // 147

#define FLG_AGG  (1ULL << 62)
#define FLG_INC  (2ULL << 62)

// ---------------- scratch (device globals; zero-initialized at load) ----------------
__device__ uint4 g_e16[TOT8];            // emb (fp16), layer-0 state
__device__ uint4 g_x1 [TOT8];            // layer-1 output (fp16)
__device__ uint4 g_x2 [TOT8];            // layer-2 output (fp16)

__device__ int2  g_edge  [N_EDGES];      // packed (src, val_fp32) grouped by dst
__device__ int   g_cnt   [N_NODES];      // degree counter; scatter returns it to 0
__device__ int   g_rowptr[N_NODES + 1];
__device__ unsigned long long g_part[NBLK];   // lookback scan state (reset every run)

// ---------------- helpers ----------------
__device__ __forceinline__ unsigned pack_h2(float a, float b) {
    __half2 h = __floats2half2_rn(a, b);
    return *reinterpret_cast<unsigned*>(&h);
}
__device__ __forceinline__ float2 unpack_h2(unsigned u) {
    return __half22float2(*reinterpret_cast<__half2*>(&u));
}

// ---------------- launch 1: convert emb -> fp16, zero scan scratch ----------------
__global__ void convert_kernel(const float* __restrict__ eu,
                               const float* __restrict__ ei) {
    int idx = blockIdx.x * blockDim.x + threadIdx.x;    // uint4 index (8 halfs)
    if (idx < N_NODES) g_cnt[idx] = 0;                  // idempotent (already 0)
    if (idx < NBLK)    g_part[idx] = 0ULL;              // reset lookback state
    if (idx >= TOT8) return;
    const int nu8 = (N_USERS * DIM) / 8;
    const float4* s;
    if (idx < nu8) s = reinterpret_cast<const float4*>(eu) + (size_t)idx * 2;
    else           s = reinterpret_cast<const float4*>(ei) + (size_t)(idx - nu8) * 2;
    float4 a = s[0], b = s[1];
    uint4 o;
    o.x = pack_h2(a.x, a.y);
    o.y = pack_h2(a.z, a.w);
    o.z = pack_h2(b.x, b.y);
    o.w = pack_h2(b.z, b.w);
    g_e16[idx] = o;
}

// ---------------- launch 2: histogram (4 edges per thread) ----------------
__global__ void hist_kernel(const int* __restrict__ dst) {
    int t = blockIdx.x * blockDim.x + threadIdx.x;
    if (t * 4 >= N_EDGES) return;
    int4 d = reinterpret_cast<const int4*>(dst)[t];
    atomicAdd(&g_cnt[d.x], 1);
    atomicAdd(&g_cnt[d.y], 1);
    atomicAdd(&g_cnt[d.z], 1);
    atomicAdd(&g_cnt[d.w], 1);
}

// ---------------- launch 3: one-pass decoupled-lookback exclusive scan ------------
__global__ void scan_kernel() {
    __shared__ int warp_tot[32];
    __shared__ int s_prefix;
    __shared__ int s_total;
    int b    = blockIdx.x;
    int gid  = b * SCAN_B + threadIdx.x;
    int lane = threadIdx.x & 31;
    int wid  = threadIdx.x >> 5;

    int v = (gid < N_NODES) ? g_cnt[gid] : 0;
    int inc = v;
    #pragma unroll
    for (int off = 1; off < 32; off <<= 1) {
        int t = __shfl_up_sync(0xFFFFFFFFu, inc, off);
        if (lane >= off) inc += t;
    }
    if (lane == 31) warp_tot[wid] = inc;
    __syncthreads();
    if (wid == 0) {
        int t = warp_tot[lane];
        int s = t;
        #pragma unroll
        for (int off = 1; off < 32; off <<= 1) {
            int u = __shfl_up_sync(0xFFFFFFFFu, s, off);
            if (lane >= off) s += u;
        }
        warp_tot[lane] = s - t;
    }
    __syncthreads();
    int ex = inc - v + warp_tot[wid];                   // exclusive within block
    if (threadIdx.x == SCAN_B - 1) s_total = ex + v;
    __syncthreads();
    int total = s_total;

    if (threadIdx.x == 0) {
        if (b == 0) {
            atomicExch(&g_part[0], FLG_INC | (unsigned long long)(unsigned)total);
            s_prefix = 0;
        } else {
            atomicExch(&g_part[b], FLG_AGG | (unsigned long long)(unsigned)total);
            int run = 0;
            int p = b - 1;
            while (true) {
                unsigned long long st  = atomicAdd(&g_part[p], 0ULL);
                unsigned long long flg = st & (3ULL << 62);
                if (flg == FLG_INC) { run += (int)(unsigned)st; break; }
                if (flg == FLG_AGG) { run += (int)(unsigned)st; p--; }
            }
            atomicExch(&g_part[b],
                       FLG_INC | (unsigned long long)(unsigned)(run + total));
            s_prefix = run;
        }
    }
    __syncthreads();
    if (gid < N_NODES) g_rowptr[gid] = ex + s_prefix;
    if (b == NBLK - 1 && threadIdx.x == 0) g_rowptr[N_NODES] = N_EDGES;
}

// ---------------- launch 4: scatter (countdown; self-resets g_cnt to 0) ----------
__global__ void scatter_kernel(const int* __restrict__ src,
                               const int* __restrict__ dst,
                               const float* __restrict__ vals) {
    int t = blockIdx.x * blockDim.x + threadIdx.x;
    if (t * 4 >= N_EDGES) return;
    int4   s4 = reinterpret_cast<const int4*>(src)[t];
    int4   d4 = reinterpret_cast<const int4*>(dst)[t];
    float4 v4 = reinterpret_cast<const float4*>(vals)[t];
    int p;
    p = g_rowptr[d4.x] + atomicSub(&g_cnt[d4.x], 1) - 1;
    g_edge[p] = make_int2(s4.x, __float_as_int(v4.x));
    p = g_rowptr[d4.y] + atomicSub(&g_cnt[d4.y], 1) - 1;
    g_edge[p] = make_int2(s4.y, __float_as_int(v4.y));
    p = g_rowptr[d4.z] + atomicSub(&g_cnt[d4.z], 1) - 1;
    g_edge[p] = make_int2(s4.z, __float_as_int(v4.z));
    p = g_rowptr[d4.w] + atomicSub(&g_cnt[d4.w], 1) - 1;
    g_edge[p] = make_int2(s4.w, __float_as_int(v4.w));
}

// ---------------- shuffle-staged row gather ----------------
// Warp holds one node's edges in registers (lane l holds edge beg+base+l,
// zero-padded past deg). (src,val) distributed by shuffle -> row-gather
// addresses are register-computed; the only memory latency is the 8
// independent row loads in flight per warp per iteration.
// Lane roles: c = lane&7 -> 16B chunk of 128B row; slot = lane>>3 in [0,4).
__device__ __forceinline__ void gather_node(const uint4* __restrict__ x,
                                            int beg, int end, int c, int slot,
                                            int lane, float (&a)[8]) {
    int deg = end - beg;
    for (int base = 0; base < deg; base += 32) {
        int2 my_e = (base + lane < deg) ? g_edge[beg + base + lane]
                                        : make_int2(0, 0);
        int m = deg - base; if (m > 32) m = 32;
        for (int k = 0; k < m; k += 8) {
            int i0 = k + slot;
            int i1 = k + 4 + slot;
            int s0 = __shfl_sync(0xFFFFFFFFu, my_e.x, i0);
            int w0 = __shfl_sync(0xFFFFFFFFu, my_e.y, i0);
            int s1 = __shfl_sync(0xFFFFFFFFu, my_e.x, i1);
            int w1 = __shfl_sync(0xFFFFFFFFu, my_e.y, i1);
            uint4 h0 = x[s0 * 8 + c];      // padded lanes: row 0 * 0.0 (L1-hot)
            uint4 h1 = x[s1 * 8 + c];
            float v0 = __int_as_float(w0);
            float v1 = __int_as_float(w1);
            float2 f;
            f = unpack_h2(h0.x); a[0] += v0 * f.x; a[1] += v0 * f.y;
            f = unpack_h2(h0.y); a[2] += v0 * f.x; a[3] += v0 * f.y;
            f = unpack_h2(h0.z); a[4] += v0 * f.x; a[5] += v0 * f.y;
            f = unpack_h2(h0.w); a[6] += v0 * f.x; a[7] += v0 * f.y;
            f = unpack_h2(h1.x); a[0] += v1 * f.x; a[1] += v1 * f.y;
            f = unpack_h2(h1.y); a[2] += v1 * f.x; a[3] += v1 * f.y;
            f = unpack_h2(h1.z); a[4] += v1 * f.x; a[5] += v1 * f.y;
            f = unpack_h2(h1.w); a[6] += v1 * f.x; a[7] += v1 * f.y;
        }
    }
    // combine the 4 slot groups
    #pragma unroll
    for (int k = 0; k < 8; k++) {
        a[k] += __shfl_xor_sync(0xFFFFFFFFu, a[k], 8);
        a[k] += __shfl_xor_sync(0xFFFFFFFFu, a[k], 16);
    }
}

// ---------------- launches 5,6: gather SpMM (fp16 state, fp32 accumulate) --------
__global__ void __launch_bounds__(256) spmm_half_kernel(
        const uint4* __restrict__ x, uint4* __restrict__ y) {
    int node = blockIdx.x * (blockDim.x >> 5) + (threadIdx.x >> 5);
    if (node >= N_NODES) return;
    int lane = threadIdx.x & 31;
    int c    = lane & 7;
    int slot = lane >> 3;

    float a[8];
    #pragma unroll
    for (int k = 0; k < 8; k++) a[k] = 0.f;

    gather_node(x, g_rowptr[node], g_rowptr[node + 1], c, slot, lane, a);

    if (slot == 0) {
        uint4 o;
        o.x = pack_h2(a[0], a[1]);
        o.y = pack_h2(a[2], a[3]);
        o.z = pack_h2(a[4], a[5]);
        o.w = pack_h2(a[6], a[7]);
        y[node * 8 + c] = o;
    }
}

// ---------------- launch 7: fused layer-3 gather + dot ---------------------------
__global__ void dot_fused_kernel(const int* __restrict__ users,
                                 const int* __restrict__ items,
                                 const float* __restrict__ eu,
                                 const float* __restrict__ ei,
                                 float* __restrict__ out) {
    int b = blockIdx.x * (blockDim.x >> 5) + (threadIdx.x >> 5);
    if (b >= BATCH) return;
    int lane = threadIdx.x & 31;
    int c    = lane & 7;
    int slot = lane >> 3;

    int u  = users[b];
    int im = items[b];
    int ni = N_USERS + im;

    float gu[8], gi[8];
    #pragma unroll
    for (int k = 0; k < 8; k++) { gu[k] = 0.f; gi[k] = 0.f; }

    gather_node(g_x2, g_rowptr[u],  g_rowptr[u  + 1], c, slot, lane, gu);
    gather_node(g_x2, g_rowptr[ni], g_rowptr[ni + 1], c, slot, lane, gi);

    const float4* pu4 = reinterpret_cast<const float4*>(eu + u  * DIM + c * 8);
    const float4* pi4 = reinterpret_cast<const float4*>(ei + im * DIM + c * 8);
    float4 bu0 = pu4[0], bu1 = pu4[1];
    float4 bi0 = pi4[0], bi1 = pi4[1];

    uint4 u1h = g_x1[u  * 8 + c], u2h = g_x2[u  * 8 + c];
    uint4 i1h = g_x1[ni * 8 + c], i2h = g_x2[ni * 8 + c];

    float ru[8], ri[8];
    {
        float2 t;
        t = unpack_h2(u1h.x); ru[0] = bu0.x + t.x; ru[1] = bu0.y + t.y;
        t = unpack_h2(u1h.y); ru[2] = bu0.z + t.x; ru[3] = bu0.w + t.y;
        t = unpack_h2(u1h.z); ru[4] = bu1.x + t.x; ru[5] = bu1.y + t.y;
        t = unpack_h2(u1h.w); ru[6] = bu1.z + t.x; ru[7] = bu1.w + t.y;
        t = unpack_h2(u2h.x); ru[0] += t.x; ru[1] += t.y;
        t = unpack_h2(u2h.y); ru[2] += t.x; ru[3] += t.y;
        t = unpack_h2(u2h.z); ru[4] += t.x; ru[5] += t.y;
        t = unpack_h2(u2h.w); ru[6] += t.x; ru[7] += t.y;

        t = unpack_h2(i1h.x); ri[0] = bi0.x + t.x; ri[1] = bi0.y + t.y;
        t = unpack_h2(i1h.y); ri[2] = bi0.z + t.x; ri[3] = bi0.w + t.y;
        t = unpack_h2(i1h.z); ri[4] = bi1.x + t.x; ri[5] = bi1.y + t.y;
        t = unpack_h2(i1h.w); ri[6] = bi1.z + t.x; ri[7] = bi1.w + t.y;
        t = unpack_h2(i2h.x); ri[0] += t.x; ri[1] += t.y;
        t = unpack_h2(i2h.y); ri[2] += t.x; ri[3] += t.y;
        t = unpack_h2(i2h.z); ri[4] += t.x; ri[5] += t.y;
        t = unpack_h2(i2h.w); ri[6] += t.x; ri[7] += t.y;
    }

    float p = 0.f;
    #pragma unroll
    for (int k = 0; k < 8; k++)
        p += (ru[k] + gu[k]) * (ri[k] + gi[k]);

    p += __shfl_xor_sync(0xFFFFFFFFu, p, 1);
    p += __shfl_xor_sync(0xFFFFFFFFu, p, 2);
    p += __shfl_xor_sync(0xFFFFFFFFu, p, 4);

    if (lane == 0)
        out[b] = p * (1.0f / 16.0f);     // (1/4)^2 mean-pool factors
}

// ---------------- launch ----------------
extern "C" void kernel_launch(void* const* d_in, const int* in_sizes, int n_in,
                              void* d_out, int out_size) {
    (void)in_sizes; (void)n_in; (void)out_size;
    const float* emb_user = (const float*)d_in[0];
    const float* emb_item = (const float*)d_in[1];
    const float* vals     = (const float*)d_in[2];
    const int*   src      = (const int*)  d_in[3];
    const int*   dst      = (const int*)  d_in[4];
    const int*   users    = (const int*)  d_in[5];
    const int*   items    = (const int*)  d_in[6];
    float* out = (float*)d_out;

    uint4 *e16, *x1, *x2;
    cudaGetSymbolAddress((void**)&e16, g_e16);
    cudaGetSymbolAddress((void**)&x1,  g_x1);
    cudaGetSymbolAddress((void**)&x2,  g_x2);

    const int T = 256;
    const int grid_cvt = (TOT8 + T - 1) / T;
    const int grid_e4  = ((N_EDGES / 4) + T - 1) / T;

    // 1: convert emb -> fp16, reset scan state
    convert_kernel<<<grid_cvt, T>>>(emb_user, emb_item);
    // 2: histogram
    hist_kernel<<<grid_e4, T>>>(dst);
    // 3: one-pass scan -> rowptr
    scan_kernel<<<NBLK, SCAN_B>>>();
    // 4: scatter (countdown; leaves g_cnt zeroed for next replay)
    scatter_kernel<<<grid_e4, T>>>(src, dst, vals);

    // 5,6: propagation (fp16 gather, fp32 accumulate)
    const int wpb = T / 32;
    const int grid_spmm = (N_NODES + wpb - 1) / wpb;
    spmm_half_kernel<<<grid_spmm, T>>>(e16, x1);   // layer 1
    spmm_half_kernel<<<grid_spmm, T>>>(x1,  x2);   // layer 2

    // 7: layer 3 fused with batched dot
    const int grid_dot = (BATCH + wpb - 1) / wpb;
    dot_fused_kernel<<<grid_dot, T>>>(users, items, emb_user, emb_item, out);
}

// round 10
// speedup vs baseline: 1.0562x; 1.0562x over previous
#include <cuda_runtime.h>
#include <cuda_fp16.h>
#include <stdint.h>

// ---------------- problem constants ----------------
#define N_USERS  50000
#define N_ITEMS  100000
#define N_NODES  (N_USERS + N_ITEMS)     // 150000
#define N_EDGES  2400000
#define DIM      64
#define BATCH    4096

#define TOTAL    (N_NODES * DIM)         // 9,600,000 floats
#define TOT8     (TOTAL / 8)             // uint4-of-half count per buffer

#define SCAN_B   1024
#define NBLK     ((N_NODES + SCAN_B - 1) / SCAN_B)   // 147

#define FLG_AGG  (1ULL << 62)
#define FLG_INC  (2ULL << 62)

#define T           256
#define HIST_BLOCKS (((N_EDGES / 4) + T - 1) / T)      // 2344
#define CVT_BLOCKS  ((TOT8 + T - 1) / T)               // 4688

// ---------------- scratch (device globals; zero-initialized at load) ----------------
__device__ uint4 g_e16[TOT8];            // emb (fp16), layer-0 state
__device__ uint4 g_x1 [TOT8];            // layer-1 output (fp16)
__device__ uint4 g_x2 [TOT8];            // layer-2 output (fp16)

__device__ int2  g_edge  [N_EDGES];      // packed (src, val_fp32) grouped by dst
__device__ int   g_cnt   [N_NODES];      // degree counter; countdown scatter returns it to 0
__device__ int   g_rowptr[N_NODES + 1];
__device__ unsigned long long g_part[NBLK];   // lookback scan state (reset every run)

// ---------------- helpers ----------------
__device__ __forceinline__ unsigned pack_h2(float a, float b) {
    __half2 h = __floats2half2_rn(a, b);
    return *reinterpret_cast<unsigned*>(&h);
}
__device__ __forceinline__ float2 unpack_h2(unsigned u) {
    return __half22float2(*reinterpret_cast<__half2*>(&u));
}

// ---------------- launch 1: histogram ∥ convert (disjoint block ranges) -----------
// hist range FIRST: its latency-bound atomic blocks start immediately; the
// streaming convert blocks backfill SM slots. Independent: hist needs only
// g_cnt == 0, maintained by the countdown scatter (and zero-init on load).
__global__ void cvt_hist_kernel(const float* __restrict__ eu,
                                const float* __restrict__ ei,
                                const int* __restrict__ dst) {
    if (blockIdx.x < HIST_BLOCKS) {
        int t = blockIdx.x * T + threadIdx.x;
        if (t < NBLK) g_part[t] = 0ULL;              // reset lookback state
        if (t * 4 >= N_EDGES) return;
        int4 d = reinterpret_cast<const int4*>(dst)[t];
        atomicAdd(&g_cnt[d.x], 1);
        atomicAdd(&g_cnt[d.y], 1);
        atomicAdd(&g_cnt[d.z], 1);
        atomicAdd(&g_cnt[d.w], 1);
    } else {
        int idx = (blockIdx.x - HIST_BLOCKS) * T + threadIdx.x;  // uint4 index
        if (idx >= TOT8) return;
        const int nu8 = (N_USERS * DIM) / 8;
        const float4* s;
        if (idx < nu8) s = reinterpret_cast<const float4*>(eu) + (size_t)idx * 2;
        else           s = reinterpret_cast<const float4*>(ei) + (size_t)(idx - nu8) * 2;
        float4 a = s[0], b = s[1];
        uint4 o;
        o.x = pack_h2(a.x, a.y);
        o.y = pack_h2(a.z, a.w);
        o.z = pack_h2(b.x, b.y);
        o.w = pack_h2(b.z, b.w);
        g_e16[idx] = o;
    }
}

// ---------------- launch 2: one-pass decoupled-lookback exclusive scan ------------
__global__ void scan_kernel() {
    __shared__ int warp_tot[32];
    __shared__ int s_prefix;
    __shared__ int s_total;
    int b    = blockIdx.x;
    int gid  = b * SCAN_B + threadIdx.x;
    int lane = threadIdx.x & 31;
    int wid  = threadIdx.x >> 5;

    int v = (gid < N_NODES) ? g_cnt[gid] : 0;
    int inc = v;
    #pragma unroll
    for (int off = 1; off < 32; off <<= 1) {
        int t = __shfl_up_sync(0xFFFFFFFFu, inc, off);
        if (lane >= off) inc += t;
    }
    if (lane == 31) warp_tot[wid] = inc;
    __syncthreads();
    if (wid == 0) {
        int t = warp_tot[lane];
        int s = t;
        #pragma unroll
        for (int off = 1; off < 32; off <<= 1) {
            int u = __shfl_up_sync(0xFFFFFFFFu, s, off);
            if (lane >= off) s += u;
        }
        warp_tot[lane] = s - t;
    }
    __syncthreads();
    int ex = inc - v + warp_tot[wid];                   // exclusive within block
    if (threadIdx.x == SCAN_B - 1) s_total = ex + v;
    __syncthreads();
    int total = s_total;

    if (threadIdx.x == 0) {
        if (b == 0) {
            atomicExch(&g_part[0], FLG_INC | (unsigned long long)(unsigned)total);
            s_prefix = 0;
        } else {
            atomicExch(&g_part[b], FLG_AGG | (unsigned long long)(unsigned)total);
            int run = 0;
            int p = b - 1;
            while (true) {
                unsigned long long st  = atomicAdd(&g_part[p], 0ULL);
                unsigned long long flg = st & (3ULL << 62);
                if (flg == FLG_INC) { run += (int)(unsigned)st; break; }
                if (flg == FLG_AGG) { run += (int)(unsigned)st; p--; }
            }
            atomicExch(&g_part[b],
                       FLG_INC | (unsigned long long)(unsigned)(run + total));
            s_prefix = run;
        }
    }
    __syncthreads();
    if (gid < N_NODES) g_rowptr[gid] = ex + s_prefix;
    if (b == NBLK - 1 && threadIdx.x == 0) g_rowptr[N_NODES] = N_EDGES;
}

// ---------------- launch 3: scatter (countdown; self-resets g_cnt to 0) ----------
__global__ void scatter_kernel(const int* __restrict__ src,
                               const int* __restrict__ dst,
                               const float* __restrict__ vals) {
    int t = blockIdx.x * blockDim.x + threadIdx.x;
    if (t * 4 >= N_EDGES) return;
    int4   s4 = reinterpret_cast<const int4*>(src)[t];
    int4   d4 = reinterpret_cast<const int4*>(dst)[t];
    float4 v4 = reinterpret_cast<const float4*>(vals)[t];
    int p;
    p = g_rowptr[d4.x] + atomicSub(&g_cnt[d4.x], 1) - 1;
    g_edge[p] = make_int2(s4.x, __float_as_int(v4.x));
    p = g_rowptr[d4.y] + atomicSub(&g_cnt[d4.y], 1) - 1;
    g_edge[p] = make_int2(s4.y, __float_as_int(v4.y));
    p = g_rowptr[d4.z] + atomicSub(&g_cnt[d4.z], 1) - 1;
    g_edge[p] = make_int2(s4.z, __float_as_int(v4.z));
    p = g_rowptr[d4.w] + atomicSub(&g_cnt[d4.w], 1) - 1;
    g_edge[p] = make_int2(s4.w, __float_as_int(v4.w));
}

// ---------------- launches 4,5: gather SpMM (fp16 state, fp32 accumulate) --------
// one warp per dst node; c = lane&7 -> 16B chunk of row; slot = lane>>3 in [0,4)
// -> edge stream; 2-deep unroll keeps 2 independent gathers in flight per lane.
__global__ void __launch_bounds__(256) spmm_half_kernel(
        const uint4* __restrict__ x, uint4* __restrict__ y) {
    int node = blockIdx.x * (blockDim.x >> 5) + (threadIdx.x >> 5);
    if (node >= N_NODES) return;
    int lane = threadIdx.x & 31;
    int c    = lane & 7;
    int slot = lane >> 3;

    int beg = g_rowptr[node];
    int end = g_rowptr[node + 1];

    float a[8];
    #pragma unroll
    for (int k = 0; k < 8; k++) a[k] = 0.f;

    int j = beg + slot;
    for (; j + 4 < end; j += 8) {
        int2  e0 = g_edge[j];
        int2  e1 = g_edge[j + 4];
        uint4 h0 = x[e0.x * 8 + c];
        uint4 h1 = x[e1.x * 8 + c];
        float v0 = __int_as_float(e0.y);
        float v1 = __int_as_float(e1.y);
        float2 f;
        f = unpack_h2(h0.x); a[0] += v0 * f.x; a[1] += v0 * f.y;
        f = unpack_h2(h0.y); a[2] += v0 * f.x; a[3] += v0 * f.y;
        f = unpack_h2(h0.z); a[4] += v0 * f.x; a[5] += v0 * f.y;
        f = unpack_h2(h0.w); a[6] += v0 * f.x; a[7] += v0 * f.y;
        f = unpack_h2(h1.x); a[0] += v1 * f.x; a[1] += v1 * f.y;
        f = unpack_h2(h1.y); a[2] += v1 * f.x; a[3] += v1 * f.y;
        f = unpack_h2(h1.z); a[4] += v1 * f.x; a[5] += v1 * f.y;
        f = unpack_h2(h1.w); a[6] += v1 * f.x; a[7] += v1 * f.y;
    }
    if (j < end) {
        int2  e0 = g_edge[j];
        uint4 h0 = x[e0.x * 8 + c];
        float v0 = __int_as_float(e0.y);
        float2 f;
        f = unpack_h2(h0.x); a[0] += v0 * f.x; a[1] += v0 * f.y;
        f = unpack_h2(h0.y); a[2] += v0 * f.x; a[3] += v0 * f.y;
        f = unpack_h2(h0.z); a[4] += v0 * f.x; a[5] += v0 * f.y;
        f = unpack_h2(h0.w); a[6] += v0 * f.x; a[7] += v0 * f.y;
    }

    #pragma unroll
    for (int k = 0; k < 8; k++) {
        a[k] += __shfl_xor_sync(0xFFFFFFFFu, a[k], 8);
        a[k] += __shfl_xor_sync(0xFFFFFFFFu, a[k], 16);
    }
    if (slot == 0) {
        uint4 o;
        o.x = pack_h2(a[0], a[1]);
        o.y = pack_h2(a[2], a[3]);
        o.z = pack_h2(a[4], a[5]);
        o.w = pack_h2(a[6], a[7]);
        y[node * 8 + c] = o;
    }
}

// ---------------- launch 6: fused layer-3 gather + dot ---------------------------
__device__ __forceinline__ void gather3_chunk(const uint4* __restrict__ x2,
                                              int node, int c, int slot,
                                              float (&g)[8]) {
    int beg = g_rowptr[node];
    int end = g_rowptr[node + 1];
    #pragma unroll
    for (int k = 0; k < 8; k++) g[k] = 0.f;
    for (int j = beg + slot; j < end; j += 4) {
        int2  ed = g_edge[j];
        float v  = __int_as_float(ed.y);
        uint4 h  = x2[ed.x * 8 + c];
        float2 f;
        f = unpack_h2(h.x); g[0] += v * f.x; g[1] += v * f.y;
        f = unpack_h2(h.y); g[2] += v * f.x; g[3] += v * f.y;
        f = unpack_h2(h.z); g[4] += v * f.x; g[5] += v * f.y;
        f = unpack_h2(h.w); g[6] += v * f.x; g[7] += v * f.y;
    }
    #pragma unroll
    for (int k = 0; k < 8; k++) {
        g[k] += __shfl_xor_sync(0xFFFFFFFFu, g[k], 8);
        g[k] += __shfl_xor_sync(0xFFFFFFFFu, g[k], 16);
    }
}

__global__ void dot_fused_kernel(const int* __restrict__ users,
                                 const int* __restrict__ items,
                                 const float* __restrict__ eu,
                                 const float* __restrict__ ei,
                                 float* __restrict__ out) {
    int b = blockIdx.x * (blockDim.x >> 5) + (threadIdx.x >> 5);
    if (b >= BATCH) return;
    int lane = threadIdx.x & 31;
    int c    = lane & 7;
    int slot = lane >> 3;

    int u  = users[b];
    int im = items[b];
    int ni = N_USERS + im;

    float gu[8], gi[8];
    gather3_chunk(g_x2, u,  c, slot, gu);
    gather3_chunk(g_x2, ni, c, slot, gi);

    const float4* pu4 = reinterpret_cast<const float4*>(eu + u  * DIM + c * 8);
    const float4* pi4 = reinterpret_cast<const float4*>(ei + im * DIM + c * 8);
    float4 bu0 = pu4[0], bu1 = pu4[1];
    float4 bi0 = pi4[0], bi1 = pi4[1];

    uint4 u1h = g_x1[u  * 8 + c], u2h = g_x2[u  * 8 + c];
    uint4 i1h = g_x1[ni * 8 + c], i2h = g_x2[ni * 8 + c];

    float ru[8], ri[8];
    {
        float2 t;
        t = unpack_h2(u1h.x); ru[0] = bu0.x + t.x; ru[1] = bu0.y + t.y;
        t = unpack_h2(u1h.y); ru[2] = bu0.z + t.x; ru[3] = bu0.w + t.y;
        t = unpack_h2(u1h.z); ru[4] = bu1.x + t.x; ru[5] = bu1.y + t.y;
        t = unpack_h2(u1h.w); ru[6] = bu1.z + t.x; ru[7] = bu1.w + t.y;
        t = unpack_h2(u2h.x); ru[0] += t.x; ru[1] += t.y;
        t = unpack_h2(u2h.y); ru[2] += t.x; ru[3] += t.y;
        t = unpack_h2(u2h.z); ru[4] += t.x; ru[5] += t.y;
        t = unpack_h2(u2h.w); ru[6] += t.x; ru[7] += t.y;

        t = unpack_h2(i1h.x); ri[0] = bi0.x + t.x; ri[1] = bi0.y + t.y;
        t = unpack_h2(i1h.y); ri[2] = bi0.z + t.x; ri[3] = bi0.w + t.y;
        t = unpack_h2(i1h.z); ri[4] = bi1.x + t.x; ri[5] = bi1.y + t.y;
        t = unpack_h2(i1h.w); ri[6] = bi1.z + t.x; ri[7] = bi1.w + t.y;
        t = unpack_h2(i2h.x); ri[0] += t.x; ri[1] += t.y;
        t = unpack_h2(i2h.y); ri[2] += t.x; ri[3] += t.y;
        t = unpack_h2(i2h.z); ri[4] += t.x; ri[5] += t.y;
        t = unpack_h2(i2h.w); ri[6] += t.x; ri[7] += t.y;
    }

    float p = 0.f;
    #pragma unroll
    for (int k = 0; k < 8; k++)
        p += (ru[k] + gu[k]) * (ri[k] + gi[k]);

    p += __shfl_xor_sync(0xFFFFFFFFu, p, 1);
    p += __shfl_xor_sync(0xFFFFFFFFu, p, 2);
    p += __shfl_xor_sync(0xFFFFFFFFu, p, 4);

    if (lane == 0)
        out[b] = p * (1.0f / 16.0f);     // (1/4)^2 mean-pool factors
}

// ---------------- launch ----------------
extern "C" void kernel_launch(void* const* d_in, const int* in_sizes, int n_in,
                              void* d_out, int out_size) {
    (void)in_sizes; (void)n_in; (void)out_size;
    const float* emb_user = (const float*)d_in[0];
    const float* emb_item = (const float*)d_in[1];
    const float* vals     = (const float*)d_in[2];
    const int*   src      = (const int*)  d_in[3];
    const int*   dst      = (const int*)  d_in[4];
    const int*   users    = (const int*)  d_in[5];
    const int*   items    = (const int*)  d_in[6];
    float* out = (float*)d_out;

    uint4 *e16, *x1, *x2;
    cudaGetSymbolAddress((void**)&e16, g_e16);
    cudaGetSymbolAddress((void**)&x1,  g_x1);
    cudaGetSymbolAddress((void**)&x2,  g_x2);

    const int grid_e4 = ((N_EDGES / 4) + T - 1) / T;

    // 1: histogram ∥ convert (disjoint block ranges; hist first)
    cvt_hist_kernel<<<HIST_BLOCKS + CVT_BLOCKS, T>>>(emb_user, emb_item, dst);
    // 2: one-pass scan -> rowptr
    scan_kernel<<<NBLK, SCAN_B>>>();
    // 3: scatter (countdown; leaves g_cnt zeroed for next replay)
    scatter_kernel<<<grid_e4, T>>>(src, dst, vals);

    // 4,5: propagation (fp16 gather, fp32 accumulate)
    const int wpb = T / 32;
    const int grid_spmm = (N_NODES + wpb - 1) / wpb;
    spmm_half_kernel<<<grid_spmm, T>>>(e16, x1);   // layer 1
    spmm_half_kernel<<<grid_spmm, T>>>(x1,  x2);   // layer 2

    // 6: layer 3 fused with batched dot
    const int grid_dot = (BATCH + wpb - 1) / wpb;
    dot_fused_kernel<<<grid_dot, T>>>(users, items, emb_user, emb_item, out);
}

// round 11
// speedup vs baseline: 1.0967x; 1.0383x over previous
#include <cuda_runtime.h>
#include <cuda_fp16.h>
#include <stdint.h>

// ---------------- problem constants ----------------
#define N_USERS  50000
#define N_ITEMS  100000
#define N_NODES  (N_USERS + N_ITEMS)     // 150000
#define N_EDGES  2400000
#define DIM      64
#define BATCH    4096

#define TOTAL    (N_NODES * DIM)         // 9,600,000 floats
#define TOT8     (TOTAL / 8)             // uint4-of-half count per buffer

#define SCAN_B   1024
#define NBLK     ((N_NODES + SCAN_B - 1) / SCAN_B)   // 147

#define FLG_AGG  (1ULL << 62)
#define FLG_INC  (2ULL << 62)

#define T           256
#define HIST_BLOCKS (((N_EDGES / 4) + T - 1) / T)      // 2344
#define SCT_BLOCKS  HIST_BLOCKS
#define CVT_BLOCKS  ((TOT8 + T - 1) / T)               // 4688

// ---------------- scratch (device globals; zero-initialized at load) ----------------
// TWO state buffers (fp16): bufA = emb -> layer-2 output; bufB = layer-1 output.
// L1: A->B, L2: B->A (A's emb content is dead after L1). Dot: x1=B, x2=A.
__device__ uint4 g_bufA[TOT8];
__device__ uint4 g_bufB[TOT8];

__device__ int2  g_edge  [N_EDGES];      // packed (src, val_fp32) grouped by dst
__device__ int   g_cnt   [N_NODES];      // degree counter; countdown scatter returns it to 0
__device__ int   g_rowptr[N_NODES + 1];
__device__ unsigned long long g_part[NBLK];   // lookback scan state (reset every run)

// ---------------- helpers ----------------
__device__ __forceinline__ unsigned pack_h2(float a, float b) {
    __half2 h = __floats2half2_rn(a, b);
    return *reinterpret_cast<unsigned*>(&h);
}
__device__ __forceinline__ float2 unpack_h2(unsigned u) {
    return __half22float2(*reinterpret_cast<__half2*>(&u));
}

// ---------------- launch 1: histogram (+ g_part reset) ----------------------------
__global__ void hist_kernel(const int* __restrict__ dst) {
    int t = blockIdx.x * blockDim.x + threadIdx.x;
    if (t < NBLK) g_part[t] = 0ULL;                  // reset lookback state
    if (t * 4 >= N_EDGES) return;
    int4 d = reinterpret_cast<const int4*>(dst)[t];
    atomicAdd(&g_cnt[d.x], 1);
    atomicAdd(&g_cnt[d.y], 1);
    atomicAdd(&g_cnt[d.z], 1);
    atomicAdd(&g_cnt[d.w], 1);
}

// ---------------- launch 2: one-pass decoupled-lookback exclusive scan ------------
__global__ void scan_kernel() {
    __shared__ int warp_tot[32];
    __shared__ int s_prefix;
    __shared__ int s_total;
    int b    = blockIdx.x;
    int gid  = b * SCAN_B + threadIdx.x;
    int lane = threadIdx.x & 31;
    int wid  = threadIdx.x >> 5;

    int v = (gid < N_NODES) ? g_cnt[gid] : 0;
    int inc = v;
    #pragma unroll
    for (int off = 1; off < 32; off <<= 1) {
        int t = __shfl_up_sync(0xFFFFFFFFu, inc, off);
        if (lane >= off) inc += t;
    }
    if (lane == 31) warp_tot[wid] = inc;
    __syncthreads();
    if (wid == 0) {
        int t = warp_tot[lane];
        int s = t;
        #pragma unroll
        for (int off = 1; off < 32; off <<= 1) {
            int u = __shfl_up_sync(0xFFFFFFFFu, s, off);
            if (lane >= off) s += u;
        }
        warp_tot[lane] = s - t;
    }
    __syncthreads();
    int ex = inc - v + warp_tot[wid];                   // exclusive within block
    if (threadIdx.x == SCAN_B - 1) s_total = ex + v;
    __syncthreads();
    int total = s_total;

    if (threadIdx.x == 0) {
        if (b == 0) {
            atomicExch(&g_part[0], FLG_INC | (unsigned long long)(unsigned)total);
            s_prefix = 0;
        } else {
            atomicExch(&g_part[b], FLG_AGG | (unsigned long long)(unsigned)total);
            int run = 0;
            int p = b - 1;
            while (true) {
                unsigned long long st  = atomicAdd(&g_part[p], 0ULL);
                unsigned long long flg = st & (3ULL << 62);
                if (flg == FLG_INC) { run += (int)(unsigned)st; break; }
                if (flg == FLG_AGG) { run += (int)(unsigned)st; p--; }
            }
            atomicExch(&g_part[b],
                       FLG_INC | (unsigned long long)(unsigned)(run + total));
            s_prefix = run;
        }
    }
    __syncthreads();
    if (gid < N_NODES) g_rowptr[gid] = ex + s_prefix;
    if (b == NBLK - 1 && threadIdx.x == 0) g_rowptr[N_NODES] = N_EDGES;
}

// ---------------- launch 3: scatter ∥ convert (disjoint block ranges) -------------
// scatter range FIRST (latency-bound countdown atomics start immediately);
// streaming convert backfills. Both only depend on scan (scatter) / nothing
// (convert), and both must finish before SpMM layer 1.
__global__ void sct_cvt_kernel(const int* __restrict__ src,
                               const int* __restrict__ dst,
                               const float* __restrict__ vals,
                               const float* __restrict__ eu,
                               const float* __restrict__ ei) {
    if (blockIdx.x < SCT_BLOCKS) {
        int t = blockIdx.x * T + threadIdx.x;
        if (t * 4 >= N_EDGES) return;
        int4   s4 = reinterpret_cast<const int4*>(src)[t];
        int4   d4 = reinterpret_cast<const int4*>(dst)[t];
        float4 v4 = reinterpret_cast<const float4*>(vals)[t];
        int p;
        p = g_rowptr[d4.x] + atomicSub(&g_cnt[d4.x], 1) - 1;
        g_edge[p] = make_int2(s4.x, __float_as_int(v4.x));
        p = g_rowptr[d4.y] + atomicSub(&g_cnt[d4.y], 1) - 1;
        g_edge[p] = make_int2(s4.y, __float_as_int(v4.y));
        p = g_rowptr[d4.z] + atomicSub(&g_cnt[d4.z], 1) - 1;
        g_edge[p] = make_int2(s4.z, __float_as_int(v4.z));
        p = g_rowptr[d4.w] + atomicSub(&g_cnt[d4.w], 1) - 1;
        g_edge[p] = make_int2(s4.w, __float_as_int(v4.w));
    } else {
        int idx = (blockIdx.x - SCT_BLOCKS) * T + threadIdx.x;   // uint4 index
        if (idx >= TOT8) return;
        const int nu8 = (N_USERS * DIM) / 8;
        const float4* s;
        if (idx < nu8) s = reinterpret_cast<const float4*>(eu) + (size_t)idx * 2;
        else           s = reinterpret_cast<const float4*>(ei) + (size_t)(idx - nu8) * 2;
        float4 a = s[0], b = s[1];
        uint4 o;
        o.x = pack_h2(a.x, a.y);
        o.y = pack_h2(a.z, a.w);
        o.z = pack_h2(b.x, b.y);
        o.w = pack_h2(b.z, b.w);
        g_bufA[idx] = o;
    }
}

// ---------------- launches 4,5: gather SpMM (fp16 state, fp32 accumulate) --------
// one warp per dst node; c = lane&7 -> 16B chunk of row; slot = lane>>3 in [0,4)
// -> edge stream; 2-deep unroll keeps 2 independent gathers in flight per lane.
__global__ void __launch_bounds__(256) spmm_half_kernel(
        const uint4* __restrict__ x, uint4* __restrict__ y) {
    int node = blockIdx.x * (blockDim.x >> 5) + (threadIdx.x >> 5);
    if (node >= N_NODES) return;
    int lane = threadIdx.x & 31;
    int c    = lane & 7;
    int slot = lane >> 3;

    int beg = g_rowptr[node];
    int end = g_rowptr[node + 1];

    float a[8];
    #pragma unroll
    for (int k = 0; k < 8; k++) a[k] = 0.f;

    int j = beg + slot;
    for (; j + 4 < end; j += 8) {
        int2  e0 = g_edge[j];
        int2  e1 = g_edge[j + 4];
        uint4 h0 = x[e0.x * 8 + c];
        uint4 h1 = x[e1.x * 8 + c];
        float v0 = __int_as_float(e0.y);
        float v1 = __int_as_float(e1.y);
        float2 f;
        f = unpack_h2(h0.x); a[0] += v0 * f.x; a[1] += v0 * f.y;
        f = unpack_h2(h0.y); a[2] += v0 * f.x; a[3] += v0 * f.y;
        f = unpack_h2(h0.z); a[4] += v0 * f.x; a[5] += v0 * f.y;
        f = unpack_h2(h0.w); a[6] += v0 * f.x; a[7] += v0 * f.y;
        f = unpack_h2(h1.x); a[0] += v1 * f.x; a[1] += v1 * f.y;
        f = unpack_h2(h1.y); a[2] += v1 * f.x; a[3] += v1 * f.y;
        f = unpack_h2(h1.z); a[4] += v1 * f.x; a[5] += v1 * f.y;
        f = unpack_h2(h1.w); a[6] += v1 * f.x; a[7] += v1 * f.y;
    }
    if (j < end) {
        int2  e0 = g_edge[j];
        uint4 h0 = x[e0.x * 8 + c];
        float v0 = __int_as_float(e0.y);
        float2 f;
        f = unpack_h2(h0.x); a[0] += v0 * f.x; a[1] += v0 * f.y;
        f = unpack_h2(h0.y); a[2] += v0 * f.x; a[3] += v0 * f.y;
        f = unpack_h2(h0.z); a[4] += v0 * f.x; a[5] += v0 * f.y;
        f = unpack_h2(h0.w); a[6] += v0 * f.x; a[7] += v0 * f.y;
    }

    #pragma unroll
    for (int k = 0; k < 8; k++) {
        a[k] += __shfl_xor_sync(0xFFFFFFFFu, a[k], 8);
        a[k] += __shfl_xor_sync(0xFFFFFFFFu, a[k], 16);
    }
    if (slot == 0) {
        uint4 o;
        o.x = pack_h2(a[0], a[1]);
        o.y = pack_h2(a[2], a[3]);
        o.z = pack_h2(a[4], a[5]);
        o.w = pack_h2(a[6], a[7]);
        y[node * 8 + c] = o;
    }
}

// ---------------- launch 6: fused layer-3 gather + dot ---------------------------
__device__ __forceinline__ void gather3_chunk(const uint4* __restrict__ x2,
                                              int node, int c, int slot,
                                              float (&g)[8]) {
    int beg = g_rowptr[node];
    int end = g_rowptr[node + 1];
    #pragma unroll
    for (int k = 0; k < 8; k++) g[k] = 0.f;
    for (int j = beg + slot; j < end; j += 4) {
        int2  ed = g_edge[j];
        float v  = __int_as_float(ed.y);
        uint4 h  = x2[ed.x * 8 + c];
        float2 f;
        f = unpack_h2(h.x); g[0] += v * f.x; g[1] += v * f.y;
        f = unpack_h2(h.y); g[2] += v * f.x; g[3] += v * f.y;
        f = unpack_h2(h.z); g[4] += v * f.x; g[5] += v * f.y;
        f = unpack_h2(h.w); g[6] += v * f.x; g[7] += v * f.y;
    }
    #pragma unroll
    for (int k = 0; k < 8; k++) {
        g[k] += __shfl_xor_sync(0xFFFFFFFFu, g[k], 8);
        g[k] += __shfl_xor_sync(0xFFFFFFFFu, g[k], 16);
    }
}

// x1 = g_bufB (layer-1 output), x2 = g_bufA (layer-2 output)
__global__ void dot_fused_kernel(const int* __restrict__ users,
                                 const int* __restrict__ items,
                                 const float* __restrict__ eu,
                                 const float* __restrict__ ei,
                                 float* __restrict__ out) {
    int b = blockIdx.x * (blockDim.x >> 5) + (threadIdx.x >> 5);
    if (b >= BATCH) return;
    int lane = threadIdx.x & 31;
    int c    = lane & 7;
    int slot = lane >> 3;

    int u  = users[b];
    int im = items[b];
    int ni = N_USERS + im;

    float gu[8], gi[8];
    gather3_chunk(g_bufA, u,  c, slot, gu);
    gather3_chunk(g_bufA, ni, c, slot, gi);

    const float4* pu4 = reinterpret_cast<const float4*>(eu + u  * DIM + c * 8);
    const float4* pi4 = reinterpret_cast<const float4*>(ei + im * DIM + c * 8);
    float4 bu0 = pu4[0], bu1 = pu4[1];
    float4 bi0 = pi4[0], bi1 = pi4[1];

    uint4 u1h = g_bufB[u  * 8 + c], u2h = g_bufA[u  * 8 + c];
    uint4 i1h = g_bufB[ni * 8 + c], i2h = g_bufA[ni * 8 + c];

    float ru[8], ri[8];
    {
        float2 t;
        t = unpack_h2(u1h.x); ru[0] = bu0.x + t.x; ru[1] = bu0.y + t.y;
        t = unpack_h2(u1h.y); ru[2] = bu0.z + t.x; ru[3] = bu0.w + t.y;
        t = unpack_h2(u1h.z); ru[4] = bu1.x + t.x; ru[5] = bu1.y + t.y;
        t = unpack_h2(u1h.w); ru[6] = bu1.z + t.x; ru[7] = bu1.w + t.y;
        t = unpack_h2(u2h.x); ru[0] += t.x; ru[1] += t.y;
        t = unpack_h2(u2h.y); ru[2] += t.x; ru[3] += t.y;
        t = unpack_h2(u2h.z); ru[4] += t.x; ru[5] += t.y;
        t = unpack_h2(u2h.w); ru[6] += t.x; ru[7] += t.y;

        t = unpack_h2(i1h.x); ri[0] = bi0.x + t.x; ri[1] = bi0.y + t.y;
        t = unpack_h2(i1h.y); ri[2] = bi0.z + t.x; ri[3] = bi0.w + t.y;
        t = unpack_h2(i1h.z); ri[4] = bi1.x + t.x; ri[5] = bi1.y + t.y;
        t = unpack_h2(i1h.w); ri[6] = bi1.z + t.x; ri[7] = bi1.w + t.y;
        t = unpack_h2(i2h.x); ri[0] += t.x; ri[1] += t.y;
        t = unpack_h2(i2h.y); ri[2] += t.x; ri[3] += t.y;
        t = unpack_h2(i2h.z); ri[4] += t.x; ri[5] += t.y;
        t = unpack_h2(i2h.w); ri[6] += t.x; ri[7] += t.y;
    }

    float p = 0.f;
    #pragma unroll
    for (int k = 0; k < 8; k++)
        p += (ru[k] + gu[k]) * (ri[k] + gi[k]);

    p += __shfl_xor_sync(0xFFFFFFFFu, p, 1);
    p += __shfl_xor_sync(0xFFFFFFFFu, p, 2);
    p += __shfl_xor_sync(0xFFFFFFFFu, p, 4);

    if (lane == 0)
        out[b] = p * (1.0f / 16.0f);     // (1/4)^2 mean-pool factors
}

// ---------------- launch ----------------
extern "C" void kernel_launch(void* const* d_in, const int* in_sizes, int n_in,
                              void* d_out, int out_size) {
    (void)in_sizes; (void)n_in; (void)out_size;
    const float* emb_user = (const float*)d_in[0];
    const float* emb_item = (const float*)d_in[1];
    const float* vals     = (const float*)d_in[2];
    const int*   src      = (const int*)  d_in[3];
    const int*   dst      = (const int*)  d_in[4];
    const int*   users    = (const int*)  d_in[5];
    const int*   items    = (const int*)  d_in[6];
    float* out = (float*)d_out;

    uint4 *bA, *bB;
    cudaGetSymbolAddress((void**)&bA, g_bufA);
    cudaGetSymbolAddress((void**)&bB, g_bufB);

    // 1: histogram (+ g_part reset)
    hist_kernel<<<HIST_BLOCKS, T>>>(dst);
    // 2: one-pass scan -> rowptr
    scan_kernel<<<NBLK, SCAN_B>>>();
    // 3: scatter ∥ convert (scatter leaves g_cnt zeroed for next replay)
    sct_cvt_kernel<<<SCT_BLOCKS + CVT_BLOCKS, T>>>(src, dst, vals,
                                                   emb_user, emb_item);

    // 4,5: propagation (fp16 gather, fp32 accumulate), two-buffer ping-pong
    const int wpb = T / 32;
    const int grid_spmm = (N_NODES + wpb - 1) / wpb;
    spmm_half_kernel<<<grid_spmm, T>>>(bA, bB);   // layer 1: A -> B
    spmm_half_kernel<<<grid_spmm, T>>>(bB, bA);   // layer 2: B -> A (emb dead)

    // 6: layer 3 fused with batched dot (x1 = B, x2 = A)
    const int grid_dot = (BATCH + wpb - 1) / wpb;
    dot_fused_kernel<<<grid_dot, T>>>(users, items, emb_user, emb_item, out);
}